// round 13
// baseline (speedup 1.0000x reference)
#include <cuda_runtime.h>
#include <cuda_bf16.h>

// Integrate-and-fire spiking neuron, 3 phases, per-pixel independent.
// T1 = T2 = 8, L = 8, EPS = -8e-5, thre = thresh[0]/8.
//
// x layout:   x[t*S + p]   for t in [0,8), p in [0, S) with S = B*C*H*W
// out layout: out[t*S + p]
//
// R12 state of the model:
//  - Kernel is at the HBM mixed-stream floor (~70% of 8 TB/s; 268 MB total).
//  - evict_last L2 pinning across replays is a no-op at 117 MB scale (HW
//    caps the evict_last set) -> dropped.
//  - Wall-vs-ncu gap (~6.3 us) is constant across variants: replay/launch
//    overhead, not kernel-addressable.
//  - This round: 128-thread blocks (8192 CTAs) for finer scheduling
//    granularity / smaller straggler tail; occupancy identical (64 warps/SM).

#define IF_T1 8
#define IF_T2 8
#define IF_RELAX 7            // T3 - 1 = max(T1,T2) - 1
#define IF_EPS (-8e-05f)

__global__ __launch_bounds__(128)
void IF_88957362634870_kernel(const float4* __restrict__ x,
                              const float* __restrict__ thresh,
                              float4* __restrict__ out,
                              int S4) {
    int i = blockIdx.x * blockDim.x + threadIdx.x;
    if (i >= S4) return;

    // thresh/L with L=8: *0.125f is exact (power of two), matches JAX fp32.
    const float thre = __ldg(thresh) * 0.125f;

    float mem[4], sc[4];
#pragma unroll
    for (int c = 0; c < 4; c++) {
        mem[c] = 0.5f * thre;
        sc[c]  = 0.0f;
    }

    // ---- Phase 1: integrate-and-fire over T1 frames ----
    // Two batches of 4 front-batched LDG.128s (MLP=4) fit the 32-reg budget.
    // Streaming loads: input is read once per replay; L2 pinning proved a
    // no-op, so evict-first keeps L2 clean for in-flight lines.
#pragma unroll
    for (int half = 0; half < 2; half++) {
        float4 xs[4];
#pragma unroll
        for (int t = 0; t < 4; t++) {
            xs[t] = __ldcs(&x[i + (half * 4 + t) * S4]);
        }
#pragma unroll
        for (int t = 0; t < 4; t++) {
            float xv[4] = {xs[t].x, xs[t].y, xs[t].z, xs[t].w};
#pragma unroll
            for (int c = 0; c < 4; c++) {
                mem[c] = mem[c] + xv[c];
                float spike = ((mem[c] - thre) >= IF_EPS) ? thre : 0.0f;
                mem[c] = mem[c] - spike;
                sc[c]  = sc[c] + spike;
            }
        }
    }

    // ---- Phase 2: T3-1 relaxation steps with reverse spikes ----
#pragma unroll
    for (int s = 0; s < IF_RELAX; s++) {
#pragma unroll
        for (int c = 0; c < 4; c++) {
            float spike = ((mem[c] - thre) >= IF_EPS) ? thre : 0.0f;
            float rev   = ((-mem[c]) > 0.0f) ? thre : 0.0f;
            mem[c] = (mem[c] - spike) + rev;   // same assoc order as JAX
            sc[c]  = (sc[c] + spike) - rev;
        }
    }

    // ---- Phase 3: re-emit spike count as T2 output spikes ----
    // Output is write-once, never re-read: evict-first streaming stores.
#pragma unroll
    for (int c = 0; c < 4; c++) mem[c] = sc[c];

#pragma unroll
    for (int t = 0; t < IF_T2; t++) {
        float sp[4];
#pragma unroll
        for (int c = 0; c < 4; c++) {
            sp[c]  = ((mem[c] - thre) >= IF_EPS) ? thre : 0.0f;
            mem[c] = mem[c] - sp[c];
        }
        float4 o;
        o.x = sp[0]; o.y = sp[1]; o.z = sp[2]; o.w = sp[3];
        __stcs(&out[i + t * S4], o);
    }
}

extern "C" void kernel_launch(void* const* d_in, const int* in_sizes, int n_in,
                              void* d_out, int out_size) {
    const float4* x      = (const float4*)d_in[0];
    const float*  thresh = (const float*)d_in[1];
    float4*       out    = (float4*)d_out;

    // Elements per frame: total / T1; float4s per frame: /4.
    int S  = in_sizes[0] / IF_T1;
    int S4 = S / 4;

    int threads = 128;
    int blocks  = (S4 + threads - 1) / threads;
    IF_88957362634870_kernel<<<blocks, threads>>>(x, thresh, out, S4);
}